// round 2
// baseline (speedup 1.0000x reference)
#include <cuda_runtime.h>
#include <math.h>

// ---------------------------------------------------------------------------
// ImageSectionRNNCell — B=64, image 512x512x3, grid 16x16, U=256
// out layout: h_new[64*256] | c_new[64*256] | next_section[64*3]
// ---------------------------------------------------------------------------

#define B 64
#define U 256
#define IMGH 512
#define IMGW 512

__device__ float g_y[B * U];   // dense output (LSTM input x)

__device__ __forceinline__ float sigmoidf_(float x) {
    return 1.0f / (1.0f + __expf(-x));
}

// ===========================================================================
// K1: interpolate + conv1 + conv2 + dense  (one block per batch item)
// ===========================================================================
__global__ __launch_bounds__(256, 4)
void k1_front(const float* __restrict__ image,
              const float* __restrict__ section,
              const float* __restrict__ c1k, const float* __restrict__ c1b,
              const float* __restrict__ c2k, const float* __restrict__ c2b,
              const float* __restrict__ dw,  const float* __restrict__ db)
{
    const int b = blockIdx.x;
    const int t = threadIdx.x;

    __shared__ float sec[16 * 16 * 3];     // interpolated patch
    __shared__ float c1o[14 * 14 * 3];     // conv1 output
    __shared__ float xs[432];              // conv2 output (flattened x)
    __shared__ float part[4][256];         // dense split-k partials

    // ---- interpolate: thread t -> grid point (i, j) ----
    {
        const float s0 = section[b * 3 + 0];
        const float s1 = section[b * 3 + 1];
        const float ee = section[b * 3 + 2];
        const int i = t >> 4;
        const int j = t & 15;
        const float p0 = s0 + (float)i * (1.0f / 15.0f) * ee;
        const float p1 = s1 + (float)j * (1.0f / 15.0f) * ee;
        float fy = fminf(fmaxf(p0 * (float)(IMGH - 1), 0.0f), (float)(IMGH - 1));
        float fx = fminf(fmaxf(p1 * (float)(IMGW - 1), 0.0f), (float)(IMGW - 1));
        int y0 = (int)floorf(fy);
        int x0 = (int)floorf(fx);
        int y1 = min(y0 + 1, IMGH - 1);
        int x1 = min(x0 + 1, IMGW - 1);
        float wy = fy - (float)y0;
        float wx = fx - (float)x0;
        const float* img = image + (size_t)b * IMGH * IMGW * 3;
        const float* p00 = img + ((size_t)y0 * IMGW + x0) * 3;
        const float* p01 = img + ((size_t)y0 * IMGW + x1) * 3;
        const float* p10 = img + ((size_t)y1 * IMGW + x0) * 3;
        const float* p11 = img + ((size_t)y1 * IMGW + x1) * 3;
        #pragma unroll
        for (int c = 0; c < 3; c++) {
            float top = p00[c] * (1.0f - wx) + p01[c] * wx;
            float bot = p10[c] * (1.0f - wx) + p11[c] * wx;
            sec[(i * 16 + j) * 3 + c] = top * (1.0f - wy) + bot * wy;
        }
    }
    __syncthreads();

    // ---- conv1: (16,16,3) -> (14,14,3), relu ----
    for (int idx = t; idx < 14 * 14 * 3; idx += 256) {
        const int oc = idx % 3;
        const int ow = (idx / 3) % 14;
        const int oh = idx / 42;
        float acc = c1b[oc];
        #pragma unroll
        for (int kh = 0; kh < 3; kh++)
            #pragma unroll
            for (int kw = 0; kw < 3; kw++)
                #pragma unroll
                for (int ic = 0; ic < 3; ic++)
                    acc += sec[((oh + kh) * 16 + (ow + kw)) * 3 + ic] *
                           c1k[((kh * 3 + kw) * 3 + ic) * 3 + oc];
        c1o[idx] = fmaxf(acc, 0.0f);
    }
    __syncthreads();

    // ---- conv2: (14,14,3) -> (12,12,3), relu -> xs[432] ----
    for (int idx = t; idx < 12 * 12 * 3; idx += 256) {
        const int oc = idx % 3;
        const int ow = (idx / 3) % 12;
        const int oh = idx / 36;
        float acc = c2b[oc];
        #pragma unroll
        for (int kh = 0; kh < 3; kh++)
            #pragma unroll
            for (int kw = 0; kw < 3; kw++)
                #pragma unroll
                for (int ic = 0; ic < 3; ic++)
                    acc += c1o[((oh + kh) * 14 + (ow + kw)) * 3 + ic] *
                           c2k[((kh * 3 + kw) * 3 + ic) * 3 + oc];
        xs[idx] = fmaxf(acc, 0.0f);
    }
    __syncthreads();

    // ---- dense: y = relu(xs @ dw + db), split-k over 4 chunks of 108 ----
    {
        const int u4 = t & 63;   // unit group: units 4*u4 .. 4*u4+3
        const int kc = t >> 6;   // k chunk 0..3
        float4 p = make_float4(0.f, 0.f, 0.f, 0.f);
        const int k0 = kc * 108;
        #pragma unroll 4
        for (int k = k0; k < k0 + 108; k++) {
            const float xv = xs[k];
            const float4 w = *(const float4*)(dw + (size_t)k * U + u4 * 4);
            p.x += xv * w.x; p.y += xv * w.y; p.z += xv * w.z; p.w += xv * w.w;
        }
        ((float4*)part[kc])[u4] = p;
    }
    __syncthreads();
    if (t < 64) {
        float4 a0 = ((float4*)part[0])[t];
        float4 a1 = ((float4*)part[1])[t];
        float4 a2 = ((float4*)part[2])[t];
        float4 a3 = ((float4*)part[3])[t];
        const float4 bias = *(const float4*)(db + t * 4);
        float4 r;
        r.x = fmaxf(a0.x + a1.x + a2.x + a3.x + bias.x, 0.0f);
        r.y = fmaxf(a0.y + a1.y + a2.y + a3.y + bias.y, 0.0f);
        r.z = fmaxf(a0.z + a1.z + a2.z + a3.z + bias.z, 0.0f);
        r.w = fmaxf(a0.w + a1.w + a2.w + a3.w + bias.w, 0.0f);
        *(float4*)(g_y + b * U + t * 4) = r;
    }
}

// ===========================================================================
// K2: LSTM gemm + gate elementwise. Block j owns units {2j, 2j+1} for all
// 64 batches: 8 z-columns (4 gates x 2 units). 128 threads.
// Local col c = 2*g + d  (gate g, unit offset d), global col = g*256 + 2j + d.
// ===========================================================================
#define KC 128     // k-chunk size
#define APAD 132   // padded act row stride (conflict-free float4 LDS)

__global__ __launch_bounds__(128, 1)
void k2_lstm(const float* __restrict__ h0, const float* __restrict__ c0in,
             const float* __restrict__ lk, const float* __restrict__ lrk,
             const float* __restrict__ lb, float* __restrict__ out)
{
    const int j = blockIdx.x;      // unit pair
    const int t = threadIdx.x;

    __shared__ float act[64][APAD];    // act chunk [batch][k]
    __shared__ float wt[8][APAD];      // weight chunk transposed [c][k]
    __shared__ float zs[64][8];

    const int cp = t & 3;              // gate index (0..3)
    const int bp = t >> 2;             // 0..31 -> batches bp, bp+32
    const int b0 = bp, b1 = bp + 32;
    const int c0i = 2 * cp, c1i = 2 * cp + 1;

    float a00 = 0.f, a01 = 0.f, a10 = 0.f, a11 = 0.f;  // [b][c]

    for (int ch = 0; ch < 4; ch++) {
        // load act chunk: k_global = ch*128 + kk ; source g_y (ch<2) else h0
        {
            const float* src = (ch < 2) ? (g_y + ch * KC) : (h0 + (ch - 2) * KC);
            for (int i = t; i < 64 * (KC / 4); i += 128) {
                const int row  = i >> 5;        // /32
                const int col4 = i & 31;
                const float4 v = *(const float4*)(src + row * U + col4 * 4);
                *(float4*)&act[row][col4 * 4] = v;
            }
        }
        // load weight chunk transposed: thread t handles k-row t of the chunk
        {
            const float* wsrc = (ch < 2) ? lk : lrk;
            const int krow = ((ch < 2) ? ch : (ch - 2)) * KC + t;
            const float* wr = wsrc + (size_t)krow * (4 * U) + 2 * j;
            #pragma unroll
            for (int g = 0; g < 4; g++) {
                const float2 wv = *(const float2*)(wr + g * U);
                wt[2 * g + 0][t] = wv.x;
                wt[2 * g + 1][t] = wv.y;
            }
        }
        __syncthreads();

        #pragma unroll
        for (int kk = 0; kk < KC; kk += 4) {
            const float4 x0 = *(const float4*)&act[b0][kk];
            const float4 x1 = *(const float4*)&act[b1][kk];
            const float4 w0 = *(const float4*)&wt[c0i][kk];
            const float4 w1 = *(const float4*)&wt[c1i][kk];
            a00 += x0.x * w0.x + x0.y * w0.y + x0.z * w0.z + x0.w * w0.w;
            a01 += x0.x * w1.x + x0.y * w1.y + x0.z * w1.z + x0.w * w1.w;
            a10 += x1.x * w0.x + x1.y * w0.y + x1.z * w0.z + x1.w * w0.w;
            a11 += x1.x * w1.x + x1.y * w1.y + x1.z * w1.z + x1.w * w1.w;
        }
        __syncthreads();
    }

    // bias + stash into zs
    {
        const float bias0 = lb[cp * U + 2 * j + 0];
        const float bias1 = lb[cp * U + 2 * j + 1];
        zs[b0][c0i] = a00 + bias0;
        zs[b0][c1i] = a01 + bias1;
        zs[b1][c0i] = a10 + bias0;
        zs[b1][c1i] = a11 + bias1;
    }
    __syncthreads();

    // elementwise: thread t -> (batch, unit offset)
    {
        const int bb = t >> 1;
        const int d  = t & 1;
        const int u  = 2 * j + d;
        const float iz = zs[bb][0 + d];
        const float fz = zs[bb][2 + d];
        const float gz = zs[bb][4 + d];
        const float oz = zs[bb][6 + d];
        const float cprev = c0in[bb * U + u];
        const float cn = sigmoidf_(fz) * cprev + sigmoidf_(iz) * tanhf(gz);
        const float hn = sigmoidf_(oz) * tanhf(cn);
        out[bb * U + u]            = hn;
        out[B * U + bb * U + u]    = cn;
    }
}

// ===========================================================================
// K3: nsc = relu(h @ W1 + b1); next_section = sigmoid(nsc @ W2 + b2)
// one block per batch item, 256 threads
// ===========================================================================
__global__ __launch_bounds__(256, 4)
void k3_nsc(const float* __restrict__ w1, const float* __restrict__ b1,
            const float* __restrict__ w2, const float* __restrict__ b2,
            float* __restrict__ out)
{
    const int b = blockIdx.x;
    const int t = threadIdx.x;

    __shared__ float hs[U];
    __shared__ float part[4][U];
    __shared__ float ns[U];

    hs[t] = out[b * U + t];   // h_new written by K2
    __syncthreads();

    // first matmul: split-k over 4 chunks of 64
    {
        const int u4 = t & 63;
        const int kc = t >> 6;
        float4 p = make_float4(0.f, 0.f, 0.f, 0.f);
        const int k0 = kc * 64;
        #pragma unroll 4
        for (int k = k0; k < k0 + 64; k++) {
            const float hv = hs[k];
            const float4 w = *(const float4*)(w1 + (size_t)k * U + u4 * 4);
            p.x += hv * w.x; p.y += hv * w.y; p.z += hv * w.z; p.w += hv * w.w;
        }
        ((float4*)part[kc])[u4] = p;
    }
    __syncthreads();
    if (t < 64) {
        float4 a0 = ((float4*)part[0])[t];
        float4 a1 = ((float4*)part[1])[t];
        float4 a2 = ((float4*)part[2])[t];
        float4 a3 = ((float4*)part[3])[t];
        const float4 bias = *(const float4*)(b1 + t * 4);
        ns[t * 4 + 0] = fmaxf(a0.x + a1.x + a2.x + a3.x + bias.x, 0.0f);
        ns[t * 4 + 1] = fmaxf(a0.y + a1.y + a2.y + a3.y + bias.y, 0.0f);
        ns[t * 4 + 2] = fmaxf(a0.z + a1.z + a2.z + a3.z + bias.z, 0.0f);
        ns[t * 4 + 3] = fmaxf(a0.w + a1.w + a2.w + a3.w + bias.w, 0.0f);
    }
    __syncthreads();

    // second matmul: 3 outputs, one warp each
    if (t < 96) {
        const int g = t >> 5;
        const int l = t & 31;
        float s = 0.0f;
        for (int k = l; k < U; k += 32)
            s += ns[k] * w2[k * 3 + g];
        #pragma unroll
        for (int o = 16; o > 0; o >>= 1)
            s += __shfl_down_sync(0xffffffffu, s, o);
        if (l == 0)
            out[2 * B * U + b * 3 + g] = sigmoidf_(s + b2[g]);
    }
}

// ===========================================================================
extern "C" void kernel_launch(void* const* d_in, const int* in_sizes, int n_in,
                              void* d_out, int out_size)
{
    const float* image   = (const float*)d_in[0];
    const float* section = (const float*)d_in[1];
    const float* h0      = (const float*)d_in[2];
    const float* c0      = (const float*)d_in[3];
    const float* conv1_k = (const float*)d_in[4];
    const float* conv1_b = (const float*)d_in[5];
    const float* conv2_k = (const float*)d_in[6];
    const float* conv2_b = (const float*)d_in[7];
    const float* dense_w = (const float*)d_in[8];
    const float* dense_b = (const float*)d_in[9];
    const float* lstm_k  = (const float*)d_in[10];
    const float* lstm_rk = (const float*)d_in[11];
    const float* lstm_b  = (const float*)d_in[12];
    const float* nsc_w1  = (const float*)d_in[13];
    const float* nsc_b1  = (const float*)d_in[14];
    const float* nsc_w2  = (const float*)d_in[15];
    const float* nsc_b2  = (const float*)d_in[16];
    float* out = (float*)d_out;

    k1_front<<<B, 256>>>(image, section, conv1_k, conv1_b,
                         conv2_k, conv2_b, dense_w, dense_b);
    k2_lstm<<<128, 128>>>(h0, c0, lstm_k, lstm_rk, lstm_b, out);
    k3_nsc<<<B, 256>>>(nsc_w1, nsc_b1, nsc_w2, nsc_b2, out);
}